// round 1
// baseline (speedup 1.0000x reference)
#include <cuda_runtime.h>
#include <cooperative_groups.h>

namespace cg = cooperative_groups;

#define BATCH 64
#define TT    1000
#define SDIM  96
#define ADIM  32
#define HDIM  256
#define INPD  128
#define MROWS (BATCH * TT)   // 64000

// ---------------- scratch (device globals; no runtime allocation) ----------
__device__ float g_x1[MROWS * HDIM];    // relu(x @ fc_w) for current branch
__device__ float g_pre1[MROWS * HDIM];  // x1 @ W_ih + b  (branch 1)
__device__ float g_pre2[MROWS * HDIM];  // x1 @ W_ih + b  (branch 2)

// ---------------- tiled fp32 GEMM: C[M,256] = op(A[M,K] @ W[K,256] + bias) --
// BM=128, BN=64, BK=16, 256 threads, 8x4 thread tile.
// CONCAT: A is concat(state[.,96], action[.,32]) along K (boundary 96 = tile-aligned).
template <int K, bool CONCAT, bool RELU>
__global__ __launch_bounds__(256)
void gemm_kernel(const float* __restrict__ A, const float* __restrict__ A2,
                 const float* __restrict__ W, const float* __restrict__ bias1,
                 const float* __restrict__ bias2, float* __restrict__ C)
{
    constexpr int BM = 128, BN = 64, BK = 16;
    __shared__ float As[BK][BM];   // transposed: As[k][m]
    __shared__ float Bs[BK][BN];

    const int tid = threadIdx.x;
    const int tx = tid & 15;        // col group (4 cols)
    const int ty = tid >> 4;        // row group (8 rows)
    const int mBase = blockIdx.x * BM;
    const int nBase = blockIdx.y * BN;

    float acc[8][4];
#pragma unroll
    for (int i = 0; i < 8; i++)
#pragma unroll
        for (int j = 0; j < 4; j++) acc[i][j] = 0.f;

    // load mapping: lane-consecutive m (conflict-free STS), fixed k-quad per thread
    const int lm  = tid & 127;          // m within tile
    const int lk0 = (tid >> 7) * 4;     // 0 or 4

    for (int kt = 0; kt < K; kt += BK) {
        // ---- A tile: 2 float4 per thread (k-quads lk0, lk0+8) ----
#pragma unroll
        for (int l = 0; l < 2; l++) {
            const int k4 = lk0 + l * 8;
            const int gm = mBase + lm;
            const int gk = kt + k4;
            float4 v;
            if (CONCAT) {
                if (gk < SDIM) v = *(const float4*)(A  + gm * SDIM + gk);
                else           v = *(const float4*)(A2 + gm * ADIM + (gk - SDIM));
            } else {
                v = *(const float4*)(A + (size_t)gm * K + gk);
            }
            As[k4 + 0][lm] = v.x; As[k4 + 1][lm] = v.y;
            As[k4 + 2][lm] = v.z; As[k4 + 3][lm] = v.w;
        }
        // ---- B tile: 1 float4 per thread ----
        {
            const int kr = tid >> 4;
            const int c4 = (tid & 15) * 4;
            *(float4*)&Bs[kr][c4] = *(const float4*)(W + (size_t)(kt + kr) * HDIM + nBase + c4);
        }
        __syncthreads();
#pragma unroll
        for (int kk = 0; kk < BK; kk++) {
            const float4 a0 = *(const float4*)&As[kk][ty * 8];
            const float4 a1 = *(const float4*)&As[kk][ty * 8 + 4];
            const float4 bv = *(const float4*)&Bs[kk][tx * 4];
            const float av[8] = {a0.x, a0.y, a0.z, a0.w, a1.x, a1.y, a1.z, a1.w};
            const float bw[4] = {bv.x, bv.y, bv.z, bv.w};
#pragma unroll
            for (int i = 0; i < 8; i++)
#pragma unroll
                for (int j = 0; j < 4; j++)
                    acc[i][j] = fmaf(av[i], bw[j], acc[i][j]);
        }
        __syncthreads();
    }

    // ---- epilogue: bias (+bias2), optional relu, float4 stores ----
    const int gn = nBase + tx * 4;
    float4 b1 = *(const float4*)&bias1[gn];
    if (bias2 != nullptr) {
        const float4 b2 = *(const float4*)&bias2[gn];
        b1.x += b2.x; b1.y += b2.y; b1.z += b2.z; b1.w += b2.w;
    }
#pragma unroll
    for (int i = 0; i < 8; i++) {
        const int gm = mBase + ty * 8 + i;
        float4 o;
        o.x = acc[i][0] + b1.x; o.y = acc[i][1] + b1.y;
        o.z = acc[i][2] + b1.z; o.w = acc[i][3] + b1.w;
        if (RELU) {
            o.x = fmaxf(o.x, 0.f); o.y = fmaxf(o.y, 0.f);
            o.z = fmaxf(o.z, 0.f); o.w = fmaxf(o.w, 0.f);
        }
        *(float4*)(C + (size_t)gm * HDIM + gn) = o;
    }
}

// ---------------- recurrence: 2-CTA clusters, W_hh half per CTA in smem -----
// grid.x = 128: cluster id = bx/2 (0..63); branch = cid/32; 2 batch rows per cluster.
// CTA rank r owns output columns [r*128, r*128+128).
// Per step: acc = h_prev @ W_half (split K across 2 thread phases), sigmoid,
// publish h chunk to local + peer smem (DSMEM), cluster.sync, rank0 emits q.
#define WSTRIDE 260   // 256 + 4 pad: conflict-free float4 column-major W reads
#define REC_SMEM_FLOATS (128 * WSTRIDE + 1024 + 512 + 256)

__global__ void __cluster_dims__(2, 1, 1) __launch_bounds__(256, 1)
rnn_kernel(const float* __restrict__ pre1, const float* __restrict__ pre2,
           const float* __restrict__ Whh1, const float* __restrict__ Whh2,
           const float* __restrict__ qw1, const float* __restrict__ qb1,
           const float* __restrict__ qw2, const float* __restrict__ qb2,
           const float* __restrict__ hn, float* __restrict__ out)
{
    cg::cluster_group cluster = cg::this_cluster();
    const int rank = (int)cluster.block_rank();       // 0 or 1
    const int cid  = blockIdx.x >> 1;                 // 0..63
    const int branch = cid >> 5;                      // 0/1
    const int row0 = (cid & 31) * 2;                  // batch rows row0, row0+1
    const int tid = threadIdx.x;

    const float* __restrict__ pre = branch ? pre2 : pre1;
    const float* __restrict__ Whh = branch ? Whh2 : Whh1;
    const float* __restrict__ qw  = branch ? qw2 : qw1;
    const float  qb = branch ? qb2[0] : qb1[0];

    extern __shared__ float sm[];
    float* W_s  = sm;                       // [128 cols][WSTRIDE]  (col-major, padded)
    float* h_s  = sm + 128 * WSTRIDE;       // [2 bufs][2 rows][256]
    float* psum = h_s + 1024;               // [2 phase][2 rows][128]
    float* q_s  = psum + 512;               // [256]

    // load this CTA's 128 columns of W_hh (transposed into smem)
    for (int i = tid; i < 128 * 256; i += 256) {
        const int k = i >> 7;
        const int c = i & 127;
        W_s[c * WSTRIDE + k] = Whh[k * HDIM + rank * 128 + c];
    }
    q_s[tid] = qw[tid];
    // h0 into buffer 0 (full 256 cols, local copy)
    for (int i = tid; i < 512; i += 256) {
        const int r = i >> 8, k = i & 255;
        h_s[r * 256 + k] = hn[(row0 + r) * HDIM + k];
    }
    __syncthreads();
    cluster.sync();

    float* peer_h = cluster.map_shared_rank(h_s, rank ^ 1);

    const int phase = tid >> 7;                  // K half: 0 or 1
    const int col   = tid & 127;                 // local output column
    const int gcol  = rank * 128 + col;
    const float* wp = W_s + col * WSTRIDE + phase * 128;

    // prefetch pre for t=0 (finishing threads tid<128 hold the regs; their col==tid)
    float pf0 = 0.f, pf1 = 0.f;
    if (tid < 128) {
        pf0 = pre[((size_t)(row0 + 0) * TT + 0) * HDIM + gcol];
        pf1 = pre[((size_t)(row0 + 1) * TT + 0) * HDIM + gcol];
    }

    for (int t = 0; t < TT; t++) {
        const float* hr  = h_s + (t & 1) * 512;          // read buffer (h_{t-1})
        float* hw        = h_s + ((t + 1) & 1) * 512;    // write buffer (h_t)
        float* hwp       = peer_h + ((t + 1) & 1) * 512;

        float acc0 = 0.f, acc1 = 0.f;
        const float* h0p = hr + phase * 128;
        const float* h1p = hr + 256 + phase * 128;
#pragma unroll
        for (int kk = 0; kk < 128; kk += 4) {
            const float4 w = *(const float4*)(wp + kk);
            const float4 a = *(const float4*)(h0p + kk);
            const float4 b = *(const float4*)(h1p + kk);
            acc0 = fmaf(w.x, a.x, acc0); acc0 = fmaf(w.y, a.y, acc0);
            acc0 = fmaf(w.z, a.z, acc0); acc0 = fmaf(w.w, a.w, acc0);
            acc1 = fmaf(w.x, b.x, acc1); acc1 = fmaf(w.y, b.y, acc1);
            acc1 = fmaf(w.z, b.z, acc1); acc1 = fmaf(w.w, b.w, acc1);
        }
        psum[(phase * 2 + 0) * 128 + col] = acc0;
        psum[(phase * 2 + 1) * 128 + col] = acc1;
        __syncthreads();

        if (tid < 128) {
            const float v0 = psum[col]       + psum[256 + col] + pf0;
            const float v1 = psum[128 + col] + psum[384 + col] + pf1;
            const float h0v = 1.f / (1.f + __expf(-v0));
            const float h1v = 1.f / (1.f + __expf(-v1));
            hw[gcol] = h0v;  hw[256 + gcol] = h1v;     // local copy
            hwp[gcol] = h0v; hwp[256 + gcol] = h1v;    // peer copy (DSMEM)
            const int tn = (t + 1 < TT) ? (t + 1) : t; // clamp prefetch
            pf0 = pre[((size_t)(row0 + 0) * TT + tn) * HDIM + gcol];
            pf1 = pre[((size_t)(row0 + 1) * TT + tn) * HDIM + gcol];
        }
        cluster.sync();   // publishes h_t to both CTAs

        // q_t = h_t . fc2_w + fc2_b  (rank 0, one warp per batch row)
        if (rank == 0 && tid < 64) {
            const int r = tid >> 5, lane = tid & 31;
            const float* hh = hw + r * 256;
            float s = 0.f;
#pragma unroll
            for (int m = 0; m < 256; m += 32)
                s = fmaf(hh[lane + m], q_s[lane + m], s);
#pragma unroll
            for (int o = 16; o; o >>= 1)
                s += __shfl_xor_sync(0xffffffffu, s, o);
            if (lane == 0)
                out[branch * MROWS + (row0 + r) * TT + t] = s + qb;
        }
    }
}

// ---------------------------------------------------------------------------
extern "C" void kernel_launch(void* const* d_in, const int* in_sizes, int n_in,
                              void* d_out, int out_size)
{
    (void)in_sizes; (void)n_in; (void)out_size;
    const float* state  = (const float*)d_in[0];
    const float* action = (const float*)d_in[1];
    const float* hn     = (const float*)d_in[2];
    const float* fc11_w = (const float*)d_in[3];
    const float* fc11_b = (const float*)d_in[4];
    const float* W_hh1  = (const float*)d_in[5];
    const float* W_ih1  = (const float*)d_in[6];
    const float* b_hh1  = (const float*)d_in[7];
    const float* b_ih1  = (const float*)d_in[8];
    const float* fc12_w = (const float*)d_in[9];
    const float* fc12_b = (const float*)d_in[10];
    const float* fc21_w = (const float*)d_in[11];
    const float* fc21_b = (const float*)d_in[12];
    const float* W_hh2  = (const float*)d_in[13];
    const float* W_ih2  = (const float*)d_in[14];
    const float* b_hh2  = (const float*)d_in[15];
    const float* b_ih2  = (const float*)d_in[16];
    const float* fc22_w = (const float*)d_in[17];
    const float* fc22_b = (const float*)d_in[18];
    float* out = (float*)d_out;

    float *x1p, *pre1p, *pre2p;
    cudaGetSymbolAddress((void**)&x1p,  g_x1);
    cudaGetSymbolAddress((void**)&pre1p, g_pre1);
    cudaGetSymbolAddress((void**)&pre2p, g_pre2);

    const size_t rec_smem = REC_SMEM_FLOATS * sizeof(float);
    cudaFuncSetAttribute(rnn_kernel, cudaFuncAttributeMaxDynamicSharedMemorySize,
                         (int)rec_smem);

    const dim3 grid(MROWS / 128, HDIM / 64);
    const dim3 blk(256);

    // branch 1
    gemm_kernel<INPD, true,  true ><<<grid, blk>>>(state, action, fc11_w, fc11_b, nullptr, x1p);
    gemm_kernel<HDIM, false, false><<<grid, blk>>>(x1p, nullptr, W_ih1, b_hh1, b_ih1, pre1p);
    // branch 2
    gemm_kernel<INPD, true,  true ><<<grid, blk>>>(state, action, fc21_w, fc21_b, nullptr, x1p);
    gemm_kernel<HDIM, false, false><<<grid, blk>>>(x1p, nullptr, W_ih2, b_hh2, b_ih2, pre2p);
    // sequential recurrence + q projection (both branches, 64 clusters of 2 CTAs)
    rnn_kernel<<<128, blk, rec_smem>>>(pre1p, pre2p, W_hh1, W_hh2,
                                       fc12_w, fc12_b, fc22_w, fc22_b, hn, out);
}

// round 2
// speedup vs baseline: 1.2365x; 1.2365x over previous
#include <cuda_runtime.h>
#include <cooperative_groups.h>

namespace cg = cooperative_groups;

#define BATCH 64
#define TT    1000
#define SDIM  96
#define ADIM  32
#define HDIM  256
#define INPD  128
#define MROWS (BATCH * TT)   // 64000

// ---------------- scratch (device globals; no runtime allocation) ----------
__device__ float g_x1[2][MROWS * HDIM];   // relu(x @ fc_w), per branch
__device__ float g_pre[2][MROWS * HDIM];  // x1 @ W_ih + (b_hh+b_ih), per branch

// ======================= GEMM: C[M,256] = op(A @ W + bias) =================
// BM=128, BN=128, BK=8, 256 threads, 8x8 microtile, double-buffered smem.
// blockIdx.z selects branch (weights/IO pair).
template <int K, bool CONCAT, bool RELU, bool BIAS2>
__global__ __launch_bounds__(256, 2)
void gemm_kernel(const float* __restrict__ A0, const float* __restrict__ A1,
                 const float* __restrict__ Aact,
                 const float* __restrict__ W0, const float* __restrict__ W1,
                 const float* __restrict__ bA0, const float* __restrict__ bB0,
                 const float* __restrict__ bA1, const float* __restrict__ bB1,
                 float* __restrict__ C0, float* __restrict__ C1)
{
    constexpr int ASTR = 132;   // padded A-tile stride (132 mod 32 = 4; store pattern conflict-free)
    __shared__ float As[2][8][ASTR];
    __shared__ float Bs[2][8][128];

    const int z = blockIdx.z;
    const float* __restrict__ A  = z ? A1 : A0;
    const float* __restrict__ W  = z ? W1 : W0;
    const float* __restrict__ bA = z ? bA1 : bA0;
    const float* __restrict__ bB = z ? bB1 : bB0;
    float* __restrict__ C        = z ? C1 : C0;

    const int tid = threadIdx.x;
    const int mBase = blockIdx.x * 128;
    const int nBase = blockIdx.y * 128;

    const int warp = tid >> 5, lane = tid & 31;
    const int wm = warp & 1, wn = warp >> 1;        // 2x4 warp grid
    const int lx = lane & 7, ly = lane >> 3;        // 8x4 lanes
    const int rowB = wm * 64 + lx * 8;              // block-local row base
    const int colB = wn * 32 + ly * 8;              // block-local col base

    // load mapping
    const int am = tid >> 1, ak = (tid & 1) * 4;        // A: float4 along k
    const int bkr = tid >> 5, bnc = (tid & 31) * 4;     // B: float4 along n

    auto loadA = [&](int kt) -> float4 {
        const int m = mBase + am;
        const int k = kt + ak;
        if (CONCAT) {
            if (k < SDIM) return *(const float4*)(A + (size_t)m * SDIM + k);
            else          return *(const float4*)(Aact + (size_t)m * ADIM + (k - SDIM));
        }
        return *(const float4*)(A + (size_t)m * K + k);
    };

    // prologue: tile 0 straight into buffer 0
    {
        const float4 v = loadA(0);
        As[0][ak + 0][am] = v.x; As[0][ak + 1][am] = v.y;
        As[0][ak + 2][am] = v.z; As[0][ak + 3][am] = v.w;
        *(float4*)&Bs[0][bkr][bnc] = *(const float4*)(W + (size_t)bkr * HDIM + nBase + bnc);
    }
    __syncthreads();

    float acc[8][8];
#pragma unroll
    for (int i = 0; i < 8; i++)
#pragma unroll
        for (int j = 0; j < 8; j++) acc[i][j] = 0.f;

    int cur = 0;
    for (int kt = 0; kt < K; kt += 8) {
        float4 an, bn;
        const bool more = (kt + 8 < K);
        if (more) {
            an = loadA(kt + 8);
            bn = *(const float4*)(W + (size_t)(kt + 8 + bkr) * HDIM + nBase + bnc);
        }
#pragma unroll
        for (int kk = 0; kk < 8; kk++) {
            const float4 a0 = *(const float4*)&As[cur][kk][rowB];
            const float4 a1 = *(const float4*)&As[cur][kk][rowB + 4];
            const float4 b0 = *(const float4*)&Bs[cur][kk][colB];
            const float4 b1 = *(const float4*)&Bs[cur][kk][colB + 4];
            const float av[8] = {a0.x, a0.y, a0.z, a0.w, a1.x, a1.y, a1.z, a1.w};
            const float bv[8] = {b0.x, b0.y, b0.z, b0.w, b1.x, b1.y, b1.z, b1.w};
#pragma unroll
            for (int i = 0; i < 8; i++)
#pragma unroll
                for (int j = 0; j < 8; j++)
                    acc[i][j] = fmaf(av[i], bv[j], acc[i][j]);
        }
        if (more) {
            As[cur ^ 1][ak + 0][am] = an.x; As[cur ^ 1][ak + 1][am] = an.y;
            As[cur ^ 1][ak + 2][am] = an.z; As[cur ^ 1][ak + 3][am] = an.w;
            *(float4*)&Bs[cur ^ 1][bkr][bnc] = bn;
            __syncthreads();
            cur ^= 1;
        }
    }

    // epilogue
    float4 bb0 = *(const float4*)&bA[nBase + colB];
    float4 bb1 = *(const float4*)&bA[nBase + colB + 4];
    if (BIAS2) {
        const float4 c0 = *(const float4*)&bB[nBase + colB];
        const float4 c1 = *(const float4*)&bB[nBase + colB + 4];
        bb0.x += c0.x; bb0.y += c0.y; bb0.z += c0.z; bb0.w += c0.w;
        bb1.x += c1.x; bb1.y += c1.y; bb1.z += c1.z; bb1.w += c1.w;
    }
#pragma unroll
    for (int i = 0; i < 8; i++) {
        const size_t gm = mBase + rowB + i;
        float4 o0, o1;
        o0.x = acc[i][0] + bb0.x; o0.y = acc[i][1] + bb0.y;
        o0.z = acc[i][2] + bb0.z; o0.w = acc[i][3] + bb0.w;
        o1.x = acc[i][4] + bb1.x; o1.y = acc[i][5] + bb1.y;
        o1.z = acc[i][6] + bb1.z; o1.w = acc[i][7] + bb1.w;
        if (RELU) {
            o0.x = fmaxf(o0.x, 0.f); o0.y = fmaxf(o0.y, 0.f);
            o0.z = fmaxf(o0.z, 0.f); o0.w = fmaxf(o0.w, 0.f);
            o1.x = fmaxf(o1.x, 0.f); o1.y = fmaxf(o1.y, 0.f);
            o1.z = fmaxf(o1.z, 0.f); o1.w = fmaxf(o1.w, 0.f);
        }
        *(float4*)(C + gm * HDIM + nBase + colB)     = o0;
        *(float4*)(C + gm * HDIM + nBase + colB + 4) = o1;
    }
}

// ======================= recurrence ========================================
// 64 clusters x 2 CTAs (128 CTAs). Cluster cid: branch = cid/32, rows {2r, 2r+1}.
// CTA rank owns output cols [rank*128, rank*128+128). W_hh slice lives in
// REGISTERS: thread (colg = tid&31, phase = tid>>5) holds W[k0..k0+32)[4 cols]
// = 32 float4. Per step: 256 reg-FMA/thread, psum reduce over 8 phases,
// sigmoid, publish h locally + to peer (DSMEM), mbarrier handshake.

__device__ __forceinline__ void mbar_wait_cluster(uint32_t mbar, uint32_t parity)
{
    uint32_t done;
    asm volatile(
        "{\n\t.reg .pred p;\n\t"
        "mbarrier.try_wait.parity.acquire.cluster.shared::cta.b64 p, [%1], %2;\n\t"
        "selp.b32 %0, 1, 0, p;\n\t}"
        : "=r"(done) : "r"(mbar), "r"(parity) : "memory");
    if (!done) {
        asm volatile(
            "{\n\t.reg .pred P1;\n\t"
            "WL%=:\n\t"
            "mbarrier.try_wait.parity.acquire.cluster.shared::cta.b64 P1, [%0], %1, 0x989680;\n\t"
            "@P1 bra.uni WD%=;\n\t"
            "bra.uni WL%=;\n\t"
            "WD%=:\n\t}"
            :: "r"(mbar), "r"(parity) : "memory");
    }
}

__global__ void __cluster_dims__(2, 1, 1) __launch_bounds__(256, 1)
rnn_kernel(const float* __restrict__ pre1, const float* __restrict__ pre2,
           const float* __restrict__ Whh1, const float* __restrict__ Whh2,
           const float* __restrict__ qw1, const float* __restrict__ qb1,
           const float* __restrict__ qw2, const float* __restrict__ qb2,
           const float* __restrict__ hn, float* __restrict__ out)
{
    __shared__ float h_s[1024];            // [2 bufs][2 rows][256]
    __shared__ float psum[2048];           // [8 phase][2 rows][128]
    __shared__ float q_s[256];
    __shared__ alignas(8) unsigned long long mbar_s;

    cg::cluster_group cluster = cg::this_cluster();
    const int rank = (int)cluster.block_rank();        // 0 / 1
    const int cid  = blockIdx.x >> 1;
    const int branch = cid >> 5;
    const int row0 = (cid & 31) * 2;
    const int tid = threadIdx.x;

    const float* __restrict__ pre = branch ? pre2 : pre1;
    const float* __restrict__ Whh = branch ? Whh2 : Whh1;
    const float* __restrict__ qw  = branch ? qw2 : qw1;
    const float  qb = branch ? qb2[0] : qb1[0];

    const uint32_t mbar = (uint32_t)__cvta_generic_to_shared(&mbar_s);
    uint32_t peer_mbar;
    {
        const uint32_t pr = rank ^ 1;
        asm("mapa.shared::cluster.u32 %0, %1, %2;" : "=r"(peer_mbar) : "r"(mbar), "r"(pr));
    }
    float* peer_h = cluster.map_shared_rank(h_s, rank ^ 1);

    // ---- W slice into registers: 32 float4 = 128 regs ----
    const int colg  = tid & 31;     // 4-col group
    const int phase = tid >> 5;     // k block of 32
    const int k0 = phase * 32;
    float4 wreg[32];
    {
        const float* wg = Whh + (size_t)k0 * HDIM + rank * 128 + (colg << 2);
#pragma unroll
        for (int j = 0; j < 32; j++)
            wreg[j] = *(const float4*)(wg + j * HDIM);
    }
    q_s[tid] = qw[tid];
    // h0 -> buffer 0
    for (int i = tid; i < 512; i += 256) {
        const int r = i >> 8, k = i & 255;
        h_s[i] = hn[(row0 + r) * HDIM + k];
    }
    if (tid == 0) {
        asm volatile("mbarrier.init.shared.b64 [%0], %1;" :: "r"(mbar), "r"(512u) : "memory");
    }
    __syncthreads();
    cluster.sync();     // barriers + h0 visible cluster-wide

    const int rrow = tid >> 7;                 // reduce: row
    const int rcol = tid & 127;                // reduce: local col
    const int gcol = rank * 128 + rcol;
    const float* pre_base = pre + ((size_t)(row0 + rrow) * TT) * HDIM + gcol;
    float pf = pre_base[0];

    for (int t = 0; t < TT; t++) {
        const float* hr = h_s + (t & 1) * 512;
        float* hw  = h_s + ((t + 1) & 1) * 512;
        float* hwp = peer_h + ((t + 1) & 1) * 512;

        // ---- h_prev @ W (this thread: 2 rows x 4 cols, k in [k0,k0+32)) ----
        float4 a0 = {0.f, 0.f, 0.f, 0.f};
        float4 a1 = {0.f, 0.f, 0.f, 0.f};
        const float* h0 = hr + k0;
        const float* h1 = hr + 256 + k0;
#pragma unroll
        for (int j = 0; j < 32; j += 4) {
            const float4 hv0 = *(const float4*)(h0 + j);
            const float4 hv1 = *(const float4*)(h1 + j);
            const float4 w0 = wreg[j + 0], w1 = wreg[j + 1];
            const float4 w2 = wreg[j + 2], w3 = wreg[j + 3];
            a0.x = fmaf(hv0.x, w0.x, a0.x); a0.y = fmaf(hv0.x, w0.y, a0.y);
            a0.z = fmaf(hv0.x, w0.z, a0.z); a0.w = fmaf(hv0.x, w0.w, a0.w);
            a1.x = fmaf(hv1.x, w0.x, a1.x); a1.y = fmaf(hv1.x, w0.y, a1.y);
            a1.z = fmaf(hv1.x, w0.z, a1.z); a1.w = fmaf(hv1.x, w0.w, a1.w);
            a0.x = fmaf(hv0.y, w1.x, a0.x); a0.y = fmaf(hv0.y, w1.y, a0.y);
            a0.z = fmaf(hv0.y, w1.z, a0.z); a0.w = fmaf(hv0.y, w1.w, a0.w);
            a1.x = fmaf(hv1.y, w1.x, a1.x); a1.y = fmaf(hv1.y, w1.y, a1.y);
            a1.z = fmaf(hv1.y, w1.z, a1.z); a1.w = fmaf(hv1.y, w1.w, a1.w);
            a0.x = fmaf(hv0.z, w2.x, a0.x); a0.y = fmaf(hv0.z, w2.y, a0.y);
            a0.z = fmaf(hv0.z, w2.z, a0.z); a0.w = fmaf(hv0.z, w2.w, a0.w);
            a1.x = fmaf(hv1.z, w2.x, a1.x); a1.y = fmaf(hv1.z, w2.y, a1.y);
            a1.z = fmaf(hv1.z, w2.z, a1.z); a1.w = fmaf(hv1.z, w2.w, a1.w);
            a0.x = fmaf(hv0.w, w3.x, a0.x); a0.y = fmaf(hv0.w, w3.y, a0.y);
            a0.z = fmaf(hv0.w, w3.z, a0.z); a0.w = fmaf(hv0.w, w3.w, a0.w);
            a1.x = fmaf(hv1.w, w3.x, a1.x); a1.y = fmaf(hv1.w, w3.y, a1.y);
            a1.z = fmaf(hv1.w, w3.z, a1.z); a1.w = fmaf(hv1.w, w3.w, a1.w);
        }
        *(float4*)(psum + (phase * 2 + 0) * 128 + (colg << 2)) = a0;
        *(float4*)(psum + (phase * 2 + 1) * 128 + (colg << 2)) = a1;
        __syncthreads();

        // ---- reduce 8 phases, sigmoid, publish ----
        float v = pf;
#pragma unroll
        for (int p = 0; p < 8; p++) v += psum[(p * 2 + rrow) * 128 + rcol];
        const float hv = 1.f / (1.f + __expf(-v));
        hw[rrow * 256 + gcol]  = hv;     // local
        hwp[rrow * 256 + gcol] = hv;     // peer (DSMEM)
        if (t + 1 < TT) pf = pre_base[(size_t)(t + 1) * HDIM];

        asm volatile("mbarrier.arrive.shared::cta.b64 _, [%0];" :: "r"(mbar) : "memory");
        asm volatile("mbarrier.arrive.release.cluster.shared::cluster.b64 _, [%0];"
                     :: "r"(peer_mbar) : "memory");
        mbar_wait_cluster(mbar, (uint32_t)(t & 1));

        // ---- q_t for row `rank` (warp 0 of each CTA) ----
        if (tid < 32) {
            const float* hh = hw + rank * 256;
            float s = 0.f;
#pragma unroll
            for (int m = 0; m < 256; m += 32)
                s = fmaf(hh[tid + m], q_s[tid + m], s);
#pragma unroll
            for (int o = 16; o; o >>= 1)
                s += __shfl_xor_sync(0xffffffffu, s, o);
            if (tid == 0)
                out[branch * MROWS + (row0 + rank) * TT + t] = s + qb;
        }
    }
}

// ---------------------------------------------------------------------------
extern "C" void kernel_launch(void* const* d_in, const int* in_sizes, int n_in,
                              void* d_out, int out_size)
{
    (void)in_sizes; (void)n_in; (void)out_size;
    const float* state  = (const float*)d_in[0];
    const float* action = (const float*)d_in[1];
    const float* hn     = (const float*)d_in[2];
    const float* fc11_w = (const float*)d_in[3];
    const float* fc11_b = (const float*)d_in[4];
    const float* W_hh1  = (const float*)d_in[5];
    const float* W_ih1  = (const float*)d_in[6];
    const float* b_hh1  = (const float*)d_in[7];
    const float* b_ih1  = (const float*)d_in[8];
    const float* fc12_w = (const float*)d_in[9];
    const float* fc12_b = (const float*)d_in[10];
    const float* fc21_w = (const float*)d_in[11];
    const float* fc21_b = (const float*)d_in[12];
    const float* W_hh2  = (const float*)d_in[13];
    const float* W_ih2  = (const float*)d_in[14];
    const float* b_hh2  = (const float*)d_in[15];
    const float* b_ih2  = (const float*)d_in[16];
    const float* fc22_w = (const float*)d_in[17];
    const float* fc22_b = (const float*)d_in[18];
    float* out = (float*)d_out;

    float *x1p, *prep;
    cudaGetSymbolAddress((void**)&x1p, g_x1);
    cudaGetSymbolAddress((void**)&prep, g_pre);
    float* x1a  = x1p;
    float* x1b  = x1p + (size_t)MROWS * HDIM;
    float* pre1 = prep;
    float* pre2 = prep + (size_t)MROWS * HDIM;

    const dim3 grid(MROWS / 128, HDIM / 128, 2);
    const dim3 blk(256);

    // stage 1: x1[b] = relu(concat(state,action) @ fc_w[b] + fc_b[b])
    gemm_kernel<INPD, true, true, false><<<grid, blk>>>(
        state, state, action, fc11_w, fc21_w,
        fc11_b, nullptr, fc21_b, nullptr, x1a, x1b);
    // stage 2: pre[b] = x1[b] @ W_ih[b] + (b_hh[b] + b_ih[b])
    gemm_kernel<HDIM, false, false, true><<<grid, blk>>>(
        x1a, x1b, nullptr, W_ih1, W_ih2,
        b_hh1, b_ih1, b_hh2, b_ih2, pre1, pre2);
    // recurrence + q projection
    rnn_kernel<<<128, blk>>>(pre1, pre2, W_hh1, W_hh2,
                             fc12_w, fc12_b, fc22_w, fc22_b, hn, out);
}